// round 2
// baseline (speedup 1.0000x reference)
#include <cuda_runtime.h>

#define NTOT 16384   // B*N
#define NPTS 8192    // N (per batch)
#define KNN  16
#define DOUT 128

// ---- scratch (__device__ globals: allocation-free) ----
__device__ float4 g_keys[NTOT];          // packed (x, y, z, ||k||^2)
__device__ float  g_Q[NTOT * DOUT];      // points1 @ W1^T + bias
__device__ float  g_P[NTOT * DOUT];      // points2 @ W2^T
__device__ int    g_id[NTOT * KNN];
__device__ float  g_w[NTOT * KNN];

// ============================================================
// 1) pack keys: (x, y, z, x^2+y^2+z^2) with reference rounding
// ============================================================
__global__ void pack_kernel(const float* __restrict__ xyz1) {
    int t = blockIdx.x * blockDim.x + threadIdx.x;
    if (t >= NTOT) return;
    float x = xyz1[3 * t + 0];
    float y = xyz1[3 * t + 1];
    float z = xyz1[3 * t + 2];
    float n = __fadd_rn(__fadd_rn(__fmul_rn(x, x), __fmul_rn(y, y)), __fmul_rn(z, z));
    g_keys[t] = make_float4(x, y, z, n);
}

// ============================================================
// 2) top-16 nearest neighbors + inverse-distance weights.
//    Distance replicates the reference op-for-op:
//      dot = (qx*kx + qy*ky) + qz*kz
//      d2  = (qn + kn) - 2*dot        (each op separately rounded)
//    thread-per-query; full key set (128KB) in dynamic smem.
// ============================================================
__global__ void __launch_bounds__(128) topk_kernel(const float* __restrict__ xyz2) {
    extern __shared__ float4 skeys[];
    int tid = threadIdx.x;
    int q = blockIdx.x * 128 + tid;          // global query id
    int b = q >> 13;                         // batch
    const float4* gk = g_keys + (b << 13);
    for (int i = tid; i < NPTS; i += 128) skeys[i] = gk[i];
    __syncthreads();

    float qx = xyz2[3 * q + 0];
    float qy = xyz2[3 * q + 1];
    float qz = xyz2[3 * q + 2];
    float qn = __fadd_rn(__fadd_rn(__fmul_rn(qx, qx), __fmul_rn(qy, qy)),
                         __fmul_rn(qz, qz));

    float d[KNN];
    int   id[KNN];
#pragma unroll
    for (int j = 0; j < KNN; j++) {
        d[j] = 1e30f + (float)j * 1e24f;     // distinct sentinels (> any real d2)
        id[j] = 0;
    }
    float worst = d[KNN - 1];

#pragma unroll 4
    for (int k = 0; k < NPTS; k++) {
        float4 ky = skeys[k];
        float dot = __fadd_rn(__fadd_rn(__fmul_rn(qx, ky.x), __fmul_rn(qy, ky.y)),
                              __fmul_rn(qz, ky.z));
        float d2v = __fsub_rn(__fadd_rn(qn, ky.w), __fmul_rn(2.0f, dot));
        if (d2v < worst) {                   // strict: ties keep lower index (matches top_k)
            bool done = false;
#pragma unroll
            for (int j = 0; j < KNN; j++)
                if (!done && d[j] == worst) { d[j] = d2v; id[j] = k; done = true; }
            float a0 = fmaxf(d[0], d[1]),   a1 = fmaxf(d[2], d[3]);
            float a2 = fmaxf(d[4], d[5]),   a3 = fmaxf(d[6], d[7]);
            float a4 = fmaxf(d[8], d[9]),   a5 = fmaxf(d[10], d[11]);
            float a6 = fmaxf(d[12], d[13]), a7 = fmaxf(d[14], d[15]);
            float b0 = fmaxf(a0, a1), b1 = fmaxf(a2, a3);
            float b2 = fmaxf(a4, a5), b3 = fmaxf(a6, a7);
            worst = fmaxf(fmaxf(b0, b1), fmaxf(b2, b3));
        }
    }

    // inverse-distance weights on the same d2 values
    float r[KNN];
    float sum = 0.f;
#pragma unroll
    for (int j = 0; j < KNN; j++) {
        r[j] = __fdiv_rn(1.0f, __fadd_rn(d[j], 1e-8f));
        sum = __fadd_rn(sum, r[j]);
    }
#pragma unroll
    for (int j = 0; j < KNN; j++) {
        g_id[q * KNN + j] = id[j];
        g_w[q * KNN + j]  = __fdiv_rn(r[j], sum);
    }
}

// ============================================================
// 3) SGEMM: C[m, o] = sum_c A[m, c] * W[o, wcol0 + c] (+ bias[o])
//    128x128 block tile, 8x8 per thread, K-chunks of 16
//    dst==0 -> g_Q, dst==1 -> g_P
// ============================================================
__global__ void __launch_bounds__(256) gemm_kernel(
        const float* __restrict__ A, int K,
        const float* __restrict__ W, int wcol0,
        const float* __restrict__ bias, int dst)
{
    __shared__ float As[16][132];
    __shared__ float Bs[16][132];
    float* C = dst ? g_P : g_Q;

    int tid = threadIdx.x;
    int m0 = blockIdx.x * 128;
    int tx = tid & 15;          // 0..15 -> output cols
    int ty = tid >> 4;          // 0..15 -> output rows
    int lr = tid >> 2;          // 0..63 loader row
    int lc = (tid & 3) << 2;    // 0,4,8,12 loader k-offset

    float acc[8][8];
#pragma unroll
    for (int i = 0; i < 8; i++)
#pragma unroll
        for (int j = 0; j < 8; j++) acc[i][j] = 0.f;

    for (int kt = 0; kt < K; kt += 16) {
        float4 a0 = *(const float4*)(A + (size_t)(m0 + lr) * K + kt + lc);
        float4 a1 = *(const float4*)(A + (size_t)(m0 + lr + 64) * K + kt + lc);
        float4 b0 = *(const float4*)(W + (size_t)lr * 384 + wcol0 + kt + lc);
        float4 b1 = *(const float4*)(W + (size_t)(lr + 64) * 384 + wcol0 + kt + lc);
        __syncthreads();   // protect previous iteration's reads
        As[lc + 0][lr] = a0.x; As[lc + 1][lr] = a0.y; As[lc + 2][lr] = a0.z; As[lc + 3][lr] = a0.w;
        As[lc + 0][lr + 64] = a1.x; As[lc + 1][lr + 64] = a1.y; As[lc + 2][lr + 64] = a1.z; As[lc + 3][lr + 64] = a1.w;
        Bs[lc + 0][lr] = b0.x; Bs[lc + 1][lr] = b0.y; Bs[lc + 2][lr] = b0.z; Bs[lc + 3][lr] = b0.w;
        Bs[lc + 0][lr + 64] = b1.x; Bs[lc + 1][lr + 64] = b1.y; Bs[lc + 2][lr + 64] = b1.z; Bs[lc + 3][lr + 64] = b1.w;
        __syncthreads();
#pragma unroll
        for (int kk = 0; kk < 16; kk++) {
            float4 af0 = *(float4*)&As[kk][ty * 4];
            float4 af1 = *(float4*)&As[kk][ty * 4 + 64];
            float4 bf0 = *(float4*)&Bs[kk][tx * 4];
            float4 bf1 = *(float4*)&Bs[kk][tx * 4 + 64];
            float av[8] = {af0.x, af0.y, af0.z, af0.w, af1.x, af1.y, af1.z, af1.w};
            float bv[8] = {bf0.x, bf0.y, bf0.z, bf0.w, bf1.x, bf1.y, bf1.z, bf1.w};
#pragma unroll
            for (int i = 0; i < 8; i++)
#pragma unroll
                for (int j = 0; j < 8; j++)
                    acc[i][j] = fmaf(av[i], bv[j], acc[i][j]);
        }
    }

    float bb[8] = {0.f, 0.f, 0.f, 0.f, 0.f, 0.f, 0.f, 0.f};
    if (bias) {
        float4 x0 = *(const float4*)(bias + tx * 4);
        float4 x1 = *(const float4*)(bias + tx * 4 + 64);
        bb[0] = x0.x; bb[1] = x0.y; bb[2] = x0.z; bb[3] = x0.w;
        bb[4] = x1.x; bb[5] = x1.y; bb[6] = x1.z; bb[7] = x1.w;
    }
#pragma unroll
    for (int i = 0; i < 8; i++) {
        int row = m0 + ty * 4 + (i < 4 ? i : 64 + i - 4);
        float4 v0 = make_float4(acc[i][0] + bb[0], acc[i][1] + bb[1],
                                acc[i][2] + bb[2], acc[i][3] + bb[3]);
        float4 v1 = make_float4(acc[i][4] + bb[4], acc[i][5] + bb[5],
                                acc[i][6] + bb[6], acc[i][7] + bb[7]);
        *(float4*)(C + (size_t)row * DOUT + tx * 4) = v0;
        *(float4*)(C + (size_t)row * DOUT + tx * 4 + 64) = v1;
    }
}

// ============================================================
// 4) combine: out[q,:] = Q[q,:] + sum_k w[q,k] * P[idx[q,k],:]
// ============================================================
__global__ void __launch_bounds__(128) combine_kernel(float* __restrict__ out) {
    int q = blockIdx.x;
    int tid = threadIdx.x;
    __shared__ float sw[KNN];
    __shared__ int   sid[KNN];
    if (tid < KNN) {
        sw[tid]  = g_w[q * KNN + tid];
        sid[tid] = g_id[q * KNN + tid];
    }
    __syncthreads();
    int base = q & ~(NPTS - 1);              // batch row offset
    float acc = g_Q[(size_t)q * DOUT + tid];
#pragma unroll
    for (int j = 0; j < KNN; j++)
        acc = fmaf(sw[j], g_P[(size_t)(base + sid[j]) * DOUT + tid], acc);
    out[(size_t)q * DOUT + tid] = acc;
}

// ============================================================
// launcher
// ============================================================
extern "C" void kernel_launch(void* const* d_in, const int* in_sizes, int n_in,
                              void* d_out, int out_size) {
    const float* xyz1    = (const float*)d_in[0];
    const float* xyz2    = (const float*)d_in[1];
    const float* points1 = (const float*)d_in[2];
    const float* points2 = (const float*)d_in[3];
    const float* W       = (const float*)d_in[4];
    const float* bias    = (const float*)d_in[5];
    (void)in_sizes; (void)n_in; (void)out_size;

    cudaFuncSetAttribute(topk_kernel,
                         cudaFuncAttributeMaxDynamicSharedMemorySize, 131072);

    pack_kernel<<<(NTOT + 255) / 256, 256>>>(xyz1);
    topk_kernel<<<NTOT / 128, 128, 131072>>>(xyz2);
    gemm_kernel<<<NTOT / 128, 256>>>(points1, 128, W, 0,   bias,    0); // -> g_Q
    gemm_kernel<<<NTOT / 128, 256>>>(points2, 256, W, 128, nullptr, 1); // -> g_P
    combine_kernel<<<NTOT, 128>>>((float*)d_out);
}

// round 3
// speedup vs baseline: 1.9624x; 1.9624x over previous
#include <cuda_runtime.h>

#define NTOT 16384   // B*N
#define NPTS 8192    // N (per batch)
#define KNN  16
#define DOUT 128
#define HALF 4096    // keys per thread in topk (NPTS/2)

// ---- scratch (__device__ globals: allocation-free) ----
__device__ float4 g_keys[NTOT];          // packed (x, y, z, ||k||^2)
__device__ float  g_Q[NTOT * DOUT];      // points1 @ W1^T + bias
__device__ float  g_P[NTOT * DOUT];      // points2 @ W2^T
__device__ int    g_id[NTOT * KNN];
__device__ float  g_w[NTOT * KNN];

// ============================================================
// 1) pack keys: (x, y, z, x^2+y^2+z^2) with reference rounding
// ============================================================
__global__ void pack_kernel(const float* __restrict__ xyz1) {
    int t = blockIdx.x * blockDim.x + threadIdx.x;
    if (t >= NTOT) return;
    float x = xyz1[3 * t + 0];
    float y = xyz1[3 * t + 1];
    float z = xyz1[3 * t + 2];
    float n = __fadd_rn(__fadd_rn(__fmul_rn(x, x), __fmul_rn(y, y)), __fmul_rn(z, z));
    g_keys[t] = make_float4(x, y, z, n);
}

// ============================================================
// 2) top-16 NN: 128 blocks x 256 threads.
//    Block handles 128 queries; thread t and t+128 split the 8192
//    keys in half for the same query. Each maintains a SORTED
//    16-entry (d,id) list via branchless carry-insert; the two
//    sorted lists are merged in smem (exact top_k tie semantics).
//    Distance replicates the reference op-for-op.
// ============================================================
__global__ void __launch_bounds__(256) topk_kernel(const float* __restrict__ xyz2) {
    extern __shared__ char smraw[];
    float4* skeys = (float4*)smraw;                        // 8192*16B = 128KB
    float*  sd    = (float*)(smraw + 131072);              // [2][128][16] = 16KB
    int*    si    = (int*)  (smraw + 131072 + 16384);      // 16KB

    int tid = threadIdx.x;
    int ql  = tid & 127;          // local query
    int h   = tid >> 7;           // key half 0/1
    int q   = blockIdx.x * 128 + ql;
    int b   = q >> 13;            // batch (uniform per block: 64 blocks/batch)

    const float4* gk = g_keys + (b << 13);
    for (int i = tid; i < NPTS; i += 256) skeys[i] = gk[i];
    __syncthreads();

    float qx = xyz2[3 * q + 0];
    float qy = xyz2[3 * q + 1];
    float qz = xyz2[3 * q + 2];
    float qn = __fadd_rn(__fadd_rn(__fmul_rn(qx, qx), __fmul_rn(qy, qy)),
                         __fmul_rn(qz, qz));

    float d[KNN];
    int   id[KNN];
#pragma unroll
    for (int j = 0; j < KNN; j++) { d[j] = 3.0e38f; id[j] = 0; }

    int k0 = h * HALF;
#pragma unroll 2
    for (int kk = 0; kk < HALF; kk++) {
        int k = k0 + kk;
        float4 ky = skeys[k];
        float dot = __fadd_rn(__fadd_rn(__fmul_rn(qx, ky.x), __fmul_rn(qy, ky.y)),
                              __fmul_rn(qz, ky.z));
        float s = __fsub_rn(__fadd_rn(qn, ky.w), __fmul_rn(2.0f, dot));
        if (s < d[KNN - 1]) {
            float cv = s; int ci = k;
#pragma unroll
            for (int j = 0; j < KNN; j++) {
                bool p = cv < d[j];               // strict: ties keep earlier idx
                float od = d[j]; int oi = id[j];
                d[j]  = p ? cv : od;
                id[j] = p ? ci : oi;
                cv    = p ? od : cv;
                ci    = p ? oi : ci;
            }
        }
    }

    // publish both half-lists
    int base = ((h << 7) + ql) << 4;             // (h*128+ql)*16
#pragma unroll
    for (int j = 0; j < KNN; j++) { sd[base + j] = d[j]; si[base + j] = id[j]; }
    __syncthreads();

    if (h == 0) {
        const float* da = sd + (ql << 4);
        const float* db = sd + ((128 + ql) << 4);
        const int*   ia = si + (ql << 4);
        const int*   ib = si + ((128 + ql) << 4);
        float rd[KNN]; int rid[KNN];
        int pa = 0, pb = 0;
#pragma unroll
        for (int j = 0; j < KNN; j++) {
            float va = da[pa], vb = db[pb];
            int   xa = ia[pa], xb = ib[pb];
            bool ta = (va < vb) || (va == vb && xa < xb);  // top_k tie order
            rd[j]  = ta ? va : vb;
            rid[j] = ta ? xa : xb;
            pa += ta ? 1 : 0;
            pb += ta ? 0 : 1;
        }
        float r[KNN]; float sum = 0.f;
#pragma unroll
        for (int j = 0; j < KNN; j++) {
            r[j] = __fdiv_rn(1.0f, __fadd_rn(rd[j], 1e-8f));
            sum = __fadd_rn(sum, r[j]);
        }
#pragma unroll
        for (int j = 0; j < KNN; j++) {
            g_id[q * KNN + j] = rid[j];
            g_w[q * KNN + j]  = __fdiv_rn(r[j], sum);
        }
    }
}

// ============================================================
// 3) SGEMM: C[m, o] = sum_c A[m, c] * W[o, wcol0 + c] (+ bias[o])
//    128x128 block tile, 8x8 per thread, K-chunks of 16
// ============================================================
__global__ void __launch_bounds__(256) gemm_kernel(
        const float* __restrict__ A, int K,
        const float* __restrict__ W, int wcol0,
        const float* __restrict__ bias, int dst)
{
    __shared__ float As[16][132];
    __shared__ float Bs[16][132];
    float* C = dst ? g_P : g_Q;

    int tid = threadIdx.x;
    int m0 = blockIdx.x * 128;
    int tx = tid & 15;
    int ty = tid >> 4;
    int lr = tid >> 2;
    int lc = (tid & 3) << 2;

    float acc[8][8];
#pragma unroll
    for (int i = 0; i < 8; i++)
#pragma unroll
        for (int j = 0; j < 8; j++) acc[i][j] = 0.f;

    for (int kt = 0; kt < K; kt += 16) {
        float4 a0 = *(const float4*)(A + (size_t)(m0 + lr) * K + kt + lc);
        float4 a1 = *(const float4*)(A + (size_t)(m0 + lr + 64) * K + kt + lc);
        float4 b0 = *(const float4*)(W + (size_t)lr * 384 + wcol0 + kt + lc);
        float4 b1 = *(const float4*)(W + (size_t)(lr + 64) * 384 + wcol0 + kt + lc);
        __syncthreads();
        As[lc + 0][lr] = a0.x; As[lc + 1][lr] = a0.y; As[lc + 2][lr] = a0.z; As[lc + 3][lr] = a0.w;
        As[lc + 0][lr + 64] = a1.x; As[lc + 1][lr + 64] = a1.y; As[lc + 2][lr + 64] = a1.z; As[lc + 3][lr + 64] = a1.w;
        Bs[lc + 0][lr] = b0.x; Bs[lc + 1][lr] = b0.y; Bs[lc + 2][lr] = b0.z; Bs[lc + 3][lr] = b0.w;
        Bs[lc + 0][lr + 64] = b1.x; Bs[lc + 1][lr + 64] = b1.y; Bs[lc + 2][lr + 64] = b1.z; Bs[lc + 3][lr + 64] = b1.w;
        __syncthreads();
#pragma unroll
        for (int kk = 0; kk < 16; kk++) {
            float4 af0 = *(float4*)&As[kk][ty * 4];
            float4 af1 = *(float4*)&As[kk][ty * 4 + 64];
            float4 bf0 = *(float4*)&Bs[kk][tx * 4];
            float4 bf1 = *(float4*)&Bs[kk][tx * 4 + 64];
            float av[8] = {af0.x, af0.y, af0.z, af0.w, af1.x, af1.y, af1.z, af1.w};
            float bv[8] = {bf0.x, bf0.y, bf0.z, bf0.w, bf1.x, bf1.y, bf1.z, bf1.w};
#pragma unroll
            for (int i = 0; i < 8; i++)
#pragma unroll
                for (int j = 0; j < 8; j++)
                    acc[i][j] = fmaf(av[i], bv[j], acc[i][j]);
        }
    }

    float bb[8] = {0.f, 0.f, 0.f, 0.f, 0.f, 0.f, 0.f, 0.f};
    if (bias) {
        float4 x0 = *(const float4*)(bias + tx * 4);
        float4 x1 = *(const float4*)(bias + tx * 4 + 64);
        bb[0] = x0.x; bb[1] = x0.y; bb[2] = x0.z; bb[3] = x0.w;
        bb[4] = x1.x; bb[5] = x1.y; bb[6] = x1.z; bb[7] = x1.w;
    }
#pragma unroll
    for (int i = 0; i < 8; i++) {
        int row = m0 + ty * 4 + (i < 4 ? i : 64 + i - 4);
        float4 v0 = make_float4(acc[i][0] + bb[0], acc[i][1] + bb[1],
                                acc[i][2] + bb[2], acc[i][3] + bb[3]);
        float4 v1 = make_float4(acc[i][4] + bb[4], acc[i][5] + bb[5],
                                acc[i][6] + bb[6], acc[i][7] + bb[7]);
        *(float4*)(C + (size_t)row * DOUT + tx * 4) = v0;
        *(float4*)(C + (size_t)row * DOUT + tx * 4 + 64) = v1;
    }
}

// ============================================================
// 4) combine: out[q,:] = Q[q,:] + sum_k w[q,k] * P[idx[q,k],:]
// ============================================================
__global__ void __launch_bounds__(128) combine_kernel(float* __restrict__ out) {
    int q = blockIdx.x;
    int tid = threadIdx.x;
    __shared__ float sw[KNN];
    __shared__ int   sid[KNN];
    if (tid < KNN) {
        sw[tid]  = g_w[q * KNN + tid];
        sid[tid] = g_id[q * KNN + tid];
    }
    __syncthreads();
    int base = q & ~(NPTS - 1);
    float acc = g_Q[(size_t)q * DOUT + tid];
#pragma unroll
    for (int j = 0; j < KNN; j++)
        acc = fmaf(sw[j], g_P[(size_t)(base + sid[j]) * DOUT + tid], acc);
    out[(size_t)q * DOUT + tid] = acc;
}

// ============================================================
// launcher
// ============================================================
extern "C" void kernel_launch(void* const* d_in, const int* in_sizes, int n_in,
                              void* d_out, int out_size) {
    const float* xyz1    = (const float*)d_in[0];
    const float* xyz2    = (const float*)d_in[1];
    const float* points1 = (const float*)d_in[2];
    const float* points2 = (const float*)d_in[3];
    const float* W       = (const float*)d_in[4];
    const float* bias    = (const float*)d_in[5];
    (void)in_sizes; (void)n_in; (void)out_size;

    cudaFuncSetAttribute(topk_kernel,
                         cudaFuncAttributeMaxDynamicSharedMemorySize, 163840);

    pack_kernel<<<(NTOT + 255) / 256, 256>>>(xyz1);
    topk_kernel<<<NTOT / 128, 256, 163840>>>(xyz2);
    gemm_kernel<<<NTOT / 128, 256>>>(points1, 128, W, 0,   bias,    0); // -> g_Q
    gemm_kernel<<<NTOT / 128, 256>>>(points2, 256, W, 128, nullptr, 1); // -> g_P
    combine_kernel<<<NTOT, 128>>>((float*)d_out);
}

// round 4
// speedup vs baseline: 3.2028x; 1.6321x over previous
#include <cuda_runtime.h>

#define NTOT 16384   // B*N
#define NPTS 8192    // N (per batch)
#define KNN  16
#define DOUT 128
#define SPLIT 4
#define LKEYS 2048   // NPTS / SPLIT

// ---- scratch (__device__ globals: allocation-free) ----
__device__ float4 g_keys[NTOT];          // packed (x, y, z, ||k||^2)
__device__ float  g_Q[NTOT * DOUT];      // points1 @ W1^T + bias
__device__ float  g_P[NTOT * DOUT];      // points2 @ W2^T
__device__ int    g_id[NTOT * KNN];
__device__ float  g_w[NTOT * KNN];

// ============================================================
// f32x2 helpers (Blackwell packed fp32)
// ============================================================
__device__ __forceinline__ unsigned long long ffma2(unsigned long long a,
                                                    unsigned long long b,
                                                    unsigned long long c) {
    unsigned long long d;
    asm("fma.rn.f32x2 %0, %1, %2, %3;" : "=l"(d) : "l"(a), "l"(b), "l"(c));
    return d;
}
__device__ __forceinline__ void unpack2(float& lo, float& hi, unsigned long long v) {
    asm("mov.b64 {%0, %1}, %2;" : "=f"(lo), "=f"(hi) : "l"(v));
}

// ============================================================
// 1) pack keys: (x, y, z, x^2+y^2+z^2) with reference rounding
// ============================================================
__global__ void pack_kernel(const float* __restrict__ xyz1) {
    int t = blockIdx.x * blockDim.x + threadIdx.x;
    if (t >= NTOT) return;
    float x = xyz1[3 * t + 0];
    float y = xyz1[3 * t + 1];
    float z = xyz1[3 * t + 2];
    float n = __fadd_rn(__fadd_rn(__fmul_rn(x, x), __fmul_rn(y, y)), __fmul_rn(z, z));
    g_keys[t] = make_float4(x, y, z, n);
}

// ============================================================
// 2) top-16 NN: 128 blocks x 512 threads. 128 queries/block,
//    4-way key split. Per-lane: branch-free 2-slot candidate
//    buffer + rare warp-uniform flush into sorted 16-list.
//    4 partial lists merged in smem with exact tie order.
// ============================================================
__global__ void __launch_bounds__(512) topk_kernel(const float* __restrict__ xyz2) {
    extern __shared__ char smraw[];
    float4* skeys = (float4*)smraw;                        // 128KB
    float*  sd    = (float*)(smraw + 131072);              // [4][128][16] 32KB
    int*    si    = (int*)  (smraw + 131072 + 32768);      // 32KB

    int tid = threadIdx.x;
    int ql  = tid & 127;          // local query
    int h   = tid >> 7;           // key quarter 0..3 (uniform per warp)
    int q   = blockIdx.x * 128 + ql;
    int b   = q >> 13;            // batch (uniform per block)

    const float4* gk = g_keys + (b << 13);
    for (int i = tid; i < NPTS; i += 512) skeys[i] = gk[i];
    __syncthreads();

    float qx = xyz2[3 * q + 0];
    float qy = xyz2[3 * q + 1];
    float qz = xyz2[3 * q + 2];
    float qn = __fadd_rn(__fadd_rn(__fmul_rn(qx, qx), __fmul_rn(qy, qy)),
                         __fmul_rn(qz, qz));

    const float FINF = __int_as_float(0x7f800000);

    float d[KNN];  int id[KNN];
#pragma unroll
    for (int j = 0; j < KNN; j++) { d[j] = 3.0e38f; id[j] = 0; }

    float bd0 = FINF, bd1 = FINF;
    int   bi0 = 0,    bi1 = 0;
    int   cnt = 0;

    int k0 = h * LKEYS;
#pragma unroll 4
    for (int kk = 0; kk < LKEYS; kk++) {
        // warp-uniform flush when any lane's buffer is full
        if (__any_sync(0xffffffffu, cnt >= 2)) {
#pragma unroll
            for (int u = 0; u < 2; u++) {
                float cv = u ? bd1 : bd0;
                int   ci = u ? bi1 : bi0;
#pragma unroll
                for (int j = 0; j < KNN; j++) {
                    bool p = cv < d[j];
                    float od = d[j]; int oi = id[j];
                    d[j]  = p ? cv : od;
                    id[j] = p ? ci : oi;
                    cv    = p ? od : cv;
                    ci    = p ? oi : ci;
                }
            }
            bd0 = FINF; bd1 = FINF; cnt = 0;
        }
        int k = k0 + kk;
        float4 ky = skeys[k];                    // warp-broadcast LDS
        float dot = __fadd_rn(__fadd_rn(__fmul_rn(qx, ky.x), __fmul_rn(qy, ky.y)),
                              __fmul_rn(qz, ky.z));
        float s = __fsub_rn(__fadd_rn(qn, ky.w), __fmul_rn(2.0f, dot));
        bool p = s < d[KNN - 1];                 // stale threshold: superset, safe
        bd1 = p ? bd0 : bd1;  bi1 = p ? bi0 : bi1;
        bd0 = p ? s   : bd0;  bi0 = p ? k   : bi0;
        cnt += p ? 1 : 0;
    }
    // final flush
    {
#pragma unroll
        for (int u = 0; u < 2; u++) {
            float cv = u ? bd1 : bd0;
            int   ci = u ? bi1 : bi0;
#pragma unroll
            for (int j = 0; j < KNN; j++) {
                bool p = cv < d[j];
                float od = d[j]; int oi = id[j];
                d[j]  = p ? cv : od;
                id[j] = p ? ci : oi;
                cv    = p ? od : cv;
                ci    = p ? oi : ci;
            }
        }
    }

    // publish partial lists
    int base = (h * 128 + ql) * KNN;
#pragma unroll
    for (int j = 0; j < KNN; j++) { sd[base + j] = d[j]; si[base + j] = id[j]; }
    __syncthreads();

    // stage 1: h=0 merges lists 0,1 -> slot 0 ; h=1 merges lists 2,3 -> slot 2
    if (h < 2) {
        int la = ((2 * h + 0) * 128 + ql) * KNN;
        int lb = ((2 * h + 1) * 128 + ql) * KNN;
        float rd[KNN]; int rid[KNN];
        int pa = la, pb = lb;
#pragma unroll
        for (int j = 0; j < KNN; j++) {
            float va = sd[pa], vb = sd[pb];
            int   xa = si[pa], xb = si[pb];
            bool ta = (va < vb) || (va == vb && xa < xb);
            rd[j]  = ta ? va : vb;
            rid[j] = ta ? xa : xb;
            pa += ta ? 1 : 0;
            pb += ta ? 0 : 1;
        }
        int bo = ((2 * h) * 128 + ql) * KNN;     // write within own read set
#pragma unroll
        for (int j = 0; j < KNN; j++) { sd[bo + j] = rd[j]; si[bo + j] = rid[j]; }
    }
    __syncthreads();

    // stage 2: h=0 merges slot 0 and slot 2, computes weights, stores
    if (h == 0) {
        int la = (0 * 128 + ql) * KNN;
        int lb = (2 * 128 + ql) * KNN;
        float rd[KNN]; int rid[KNN];
        int pa = la, pb = lb;
#pragma unroll
        for (int j = 0; j < KNN; j++) {
            float va = sd[pa], vb = sd[pb];
            int   xa = si[pa], xb = si[pb];
            bool ta = (va < vb) || (va == vb && xa < xb);
            rd[j]  = ta ? va : vb;
            rid[j] = ta ? xa : xb;
            pa += ta ? 1 : 0;
            pb += ta ? 0 : 1;
        }
        float r[KNN]; float sum = 0.f;
#pragma unroll
        for (int j = 0; j < KNN; j++) {
            r[j] = __fdiv_rn(1.0f, __fadd_rn(rd[j], 1e-8f));
            sum = __fadd_rn(sum, r[j]);
        }
#pragma unroll
        for (int j = 0; j < KNN; j++) {
            g_id[q * KNN + j] = rid[j];
            g_w[q * KNN + j]  = __fdiv_rn(r[j], sum);
        }
    }
}

// ============================================================
// 3) SGEMM with f32x2 FFMA2: C[m,o] = sum_c A[m,c]*W[o,wcol0+c] (+bias)
//    A row-pairs native u64; B duplicated in smem so col-dup packs
//    are plain LDS.128.
// ============================================================
__global__ void __launch_bounds__(256) gemm_kernel(
        const float* __restrict__ A, int K,
        const float* __restrict__ W, int wcol0,
        const float* __restrict__ bias, int dst)
{
    __shared__ float As[16][132];
    __shared__ float Bs2[16][264];   // duplicated: Bs2[k][2c]=Bs2[k][2c+1]=W-val
    float* C = dst ? g_P : g_Q;

    int tid = threadIdx.x;
    int m0 = blockIdx.x * 128;
    int tx = tid & 15;
    int ty = tid >> 4;
    int lr = tid >> 2;
    int lc = (tid & 3) << 2;

    unsigned long long acc2[4][8];
#pragma unroll
    for (int i = 0; i < 4; i++)
#pragma unroll
        for (int j = 0; j < 8; j++) acc2[i][j] = 0ull;

    for (int kt = 0; kt < K; kt += 16) {
        float4 a0 = *(const float4*)(A + (size_t)(m0 + lr) * K + kt + lc);
        float4 a1 = *(const float4*)(A + (size_t)(m0 + lr + 64) * K + kt + lc);
        float4 b0 = *(const float4*)(W + (size_t)lr * 384 + wcol0 + kt + lc);
        float4 b1 = *(const float4*)(W + (size_t)(lr + 64) * 384 + wcol0 + kt + lc);
        __syncthreads();   // protect previous iteration's reads
        As[lc + 0][lr] = a0.x; As[lc + 1][lr] = a0.y; As[lc + 2][lr] = a0.z; As[lc + 3][lr] = a0.w;
        As[lc + 0][lr + 64] = a1.x; As[lc + 1][lr + 64] = a1.y; As[lc + 2][lr + 64] = a1.z; As[lc + 3][lr + 64] = a1.w;
        Bs2[lc + 0][2 * lr] = b0.x;       Bs2[lc + 0][2 * lr + 1] = b0.x;
        Bs2[lc + 1][2 * lr] = b0.y;       Bs2[lc + 1][2 * lr + 1] = b0.y;
        Bs2[lc + 2][2 * lr] = b0.z;       Bs2[lc + 2][2 * lr + 1] = b0.z;
        Bs2[lc + 3][2 * lr] = b0.w;       Bs2[lc + 3][2 * lr + 1] = b0.w;
        Bs2[lc + 0][2 * lr + 128] = b1.x; Bs2[lc + 0][2 * lr + 129] = b1.x;
        Bs2[lc + 1][2 * lr + 128] = b1.y; Bs2[lc + 1][2 * lr + 129] = b1.y;
        Bs2[lc + 2][2 * lr + 128] = b1.z; Bs2[lc + 2][2 * lr + 129] = b1.z;
        Bs2[lc + 3][2 * lr + 128] = b1.w; Bs2[lc + 3][2 * lr + 129] = b1.w;
        __syncthreads();
#pragma unroll
        for (int kk = 0; kk < 16; kk++) {
            const unsigned long long* apl = (const unsigned long long*)&As[kk][ty * 4];
            const unsigned long long* aph = (const unsigned long long*)&As[kk][ty * 4 + 64];
            unsigned long long a2[4] = { apl[0], apl[1], aph[0], aph[1] };
            const unsigned long long* bpl = (const unsigned long long*)&Bs2[kk][8 * tx];
            const unsigned long long* bph = (const unsigned long long*)&Bs2[kk][8 * tx + 128];
            unsigned long long b2[8] = { bpl[0], bpl[1], bpl[2], bpl[3],
                                         bph[0], bph[1], bph[2], bph[3] };
#pragma unroll
            for (int i = 0; i < 4; i++)
#pragma unroll
                for (int j = 0; j < 8; j++)
                    acc2[i][j] = ffma2(a2[i], b2[j], acc2[i][j]);
        }
    }

    // unpack to scalar accs (row mapping: i2<2 -> rows 2*i2,2*i2+1 ;
    // i2>=2 -> rows 64-block handled by original epilogue indexing)
    float acc[8][8];
#pragma unroll
    for (int i2 = 0; i2 < 4; i2++) {
        int ibase = (i2 < 2) ? 2 * i2 : 4 + 2 * (i2 - 2);
#pragma unroll
        for (int j = 0; j < 8; j++) {
            float lo, hi;
            unpack2(lo, hi, acc2[i2][j]);
            acc[ibase][j] = lo;
            acc[ibase + 1][j] = hi;
        }
    }

    float bb[8] = {0.f, 0.f, 0.f, 0.f, 0.f, 0.f, 0.f, 0.f};
    if (bias) {
        float4 x0 = *(const float4*)(bias + tx * 4);
        float4 x1 = *(const float4*)(bias + tx * 4 + 64);
        bb[0] = x0.x; bb[1] = x0.y; bb[2] = x0.z; bb[3] = x0.w;
        bb[4] = x1.x; bb[5] = x1.y; bb[6] = x1.z; bb[7] = x1.w;
    }
#pragma unroll
    for (int i = 0; i < 8; i++) {
        int row = m0 + ty * 4 + (i < 4 ? i : 64 + i - 4);
        float4 v0 = make_float4(acc[i][0] + bb[0], acc[i][1] + bb[1],
                                acc[i][2] + bb[2], acc[i][3] + bb[3]);
        float4 v1 = make_float4(acc[i][4] + bb[4], acc[i][5] + bb[5],
                                acc[i][6] + bb[6], acc[i][7] + bb[7]);
        *(float4*)(C + (size_t)row * DOUT + tx * 4) = v0;
        *(float4*)(C + (size_t)row * DOUT + tx * 4 + 64) = v1;
    }
}

// ============================================================
// 4) combine: out[q,:] = Q[q,:] + sum_k w[q,k] * P[idx[q,k],:]
// ============================================================
__global__ void __launch_bounds__(128) combine_kernel(float* __restrict__ out) {
    int q = blockIdx.x;
    int tid = threadIdx.x;
    __shared__ float sw[KNN];
    __shared__ int   sid[KNN];
    if (tid < KNN) {
        sw[tid]  = g_w[q * KNN + tid];
        sid[tid] = g_id[q * KNN + tid];
    }
    __syncthreads();
    int base = q & ~(NPTS - 1);
    float acc = g_Q[(size_t)q * DOUT + tid];
#pragma unroll
    for (int j = 0; j < KNN; j++)
        acc = fmaf(sw[j], g_P[(size_t)(base + sid[j]) * DOUT + tid], acc);
    out[(size_t)q * DOUT + tid] = acc;
}

// ============================================================
// launcher
// ============================================================
extern "C" void kernel_launch(void* const* d_in, const int* in_sizes, int n_in,
                              void* d_out, int out_size) {
    const float* xyz1    = (const float*)d_in[0];
    const float* xyz2    = (const float*)d_in[1];
    const float* points1 = (const float*)d_in[2];
    const float* points2 = (const float*)d_in[3];
    const float* W       = (const float*)d_in[4];
    const float* bias    = (const float*)d_in[5];
    (void)in_sizes; (void)n_in; (void)out_size;

    cudaFuncSetAttribute(topk_kernel,
                         cudaFuncAttributeMaxDynamicSharedMemorySize, 196608);

    pack_kernel<<<(NTOT + 255) / 256, 256>>>(xyz1);
    topk_kernel<<<NTOT / 128, 512, 196608>>>(xyz2);
    gemm_kernel<<<NTOT / 128, 256>>>(points1, 128, W, 0,   bias,    0); // -> g_Q
    gemm_kernel<<<NTOT / 128, 256>>>(points2, 256, W, 128, nullptr, 1); // -> g_P
    combine_kernel<<<NTOT, 128>>>((float*)d_out);
}

// round 5
// speedup vs baseline: 3.8968x; 1.2167x over previous
#include <cuda_runtime.h>

#define NTOT 16384   // B*N
#define NPTS 8192    // N (per batch)
#define KNN  16
#define DOUT 128
#define SPLIT 4
#define LKEYS 2048   // NPTS / SPLIT

// ---- scratch (__device__ globals: allocation-free) ----
__device__ float4 g_keys[NTOT];          // packed (x, y, z, ||k||^2)
__device__ float  g_Q[NTOT * DOUT];      // points1 @ W1^T + bias
__device__ float  g_P[NTOT * DOUT];      // points2 @ W2^T
__device__ int    g_id[NTOT * KNN];
__device__ float  g_w[NTOT * KNN];

// ============================================================
// 1) pack keys: (x, y, z, x^2+y^2+z^2) with reference rounding
// ============================================================
__global__ void pack_kernel(const float* __restrict__ xyz1) {
    int t = blockIdx.x * blockDim.x + threadIdx.x;
    if (t >= NTOT) return;
    float x = xyz1[3 * t + 0];
    float y = xyz1[3 * t + 1];
    float z = xyz1[3 * t + 2];
    float n = __fadd_rn(__fadd_rn(__fmul_rn(x, x), __fmul_rn(y, y)), __fmul_rn(z, z));
    g_keys[t] = make_float4(x, y, z, n);
}

// ============================================================
// 2) top-16 NN: 128 blocks x 512 threads. 128 queries/block,
//    4-way key split. Per-lane branch-free 2-slot candidate
//    buffer + warp-uniform flush into sorted 16-list.
//    4 partial lists merged in smem with exact top_k tie order.
// ============================================================
__global__ void __launch_bounds__(512) topk_kernel(const float* __restrict__ xyz2) {
    extern __shared__ char smraw[];
    float4* skeys = (float4*)smraw;                        // 128KB
    float*  sd    = (float*)(smraw + 131072);              // [4][128][16] 32KB
    int*    si    = (int*)  (smraw + 131072 + 32768);      // 32KB

    int tid = threadIdx.x;
    int ql  = tid & 127;          // local query
    int h   = tid >> 7;           // key quarter 0..3 (uniform per warp)
    int q   = blockIdx.x * 128 + ql;
    int b   = q >> 13;            // batch (uniform per block)

    const float4* gk = g_keys + (b << 13);
    for (int i = tid; i < NPTS; i += 512) skeys[i] = gk[i];
    __syncthreads();

    float qx = xyz2[3 * q + 0];
    float qy = xyz2[3 * q + 1];
    float qz = xyz2[3 * q + 2];
    float qn = __fadd_rn(__fadd_rn(__fmul_rn(qx, qx), __fmul_rn(qy, qy)),
                         __fmul_rn(qz, qz));

    const float FINF = __int_as_float(0x7f800000);

    float d[KNN];  int id[KNN];
#pragma unroll
    for (int j = 0; j < KNN; j++) { d[j] = 3.0e38f; id[j] = 0; }

    float bd0 = FINF, bd1 = FINF;
    int   bi0 = 0,    bi1 = 0;
    int   cnt = 0;

    int k0 = h * LKEYS;
#pragma unroll 4
    for (int kk = 0; kk < LKEYS; kk++) {
        if (__any_sync(0xffffffffu, cnt >= 2)) {
#pragma unroll
            for (int u = 0; u < 2; u++) {
                float cv = u ? bd1 : bd0;
                int   ci = u ? bi1 : bi0;
#pragma unroll
                for (int j = 0; j < KNN; j++) {
                    bool p = cv < d[j];
                    float od = d[j]; int oi = id[j];
                    d[j]  = p ? cv : od;
                    id[j] = p ? ci : oi;
                    cv    = p ? od : cv;
                    ci    = p ? oi : ci;
                }
            }
            bd0 = FINF; bd1 = FINF; cnt = 0;
        }
        int k = k0 + kk;
        float4 ky = skeys[k];                    // warp-broadcast LDS
        float dot = __fadd_rn(__fadd_rn(__fmul_rn(qx, ky.x), __fmul_rn(qy, ky.y)),
                              __fmul_rn(qz, ky.z));
        float s = __fsub_rn(__fadd_rn(qn, ky.w), __fmul_rn(2.0f, dot));
        bool p = s < d[KNN - 1];                 // stale threshold: superset, safe
        bd1 = p ? bd0 : bd1;  bi1 = p ? bi0 : bi1;
        bd0 = p ? s   : bd0;  bi0 = p ? k   : bi0;
        cnt += p ? 1 : 0;
    }
    // final flush
    {
#pragma unroll
        for (int u = 0; u < 2; u++) {
            float cv = u ? bd1 : bd0;
            int   ci = u ? bi1 : bi0;
#pragma unroll
            for (int j = 0; j < KNN; j++) {
                bool p = cv < d[j];
                float od = d[j]; int oi = id[j];
                d[j]  = p ? cv : od;
                id[j] = p ? ci : oi;
                cv    = p ? od : cv;
                ci    = p ? oi : ci;
            }
        }
    }

    // publish partial lists
    int base = (h * 128 + ql) * KNN;
#pragma unroll
    for (int j = 0; j < KNN; j++) { sd[base + j] = d[j]; si[base + j] = id[j]; }
    __syncthreads();

    // stage 1: h=0 merges lists 0,1 -> slot 0 ; h=1 merges lists 2,3 -> slot 2
    if (h < 2) {
        int la = ((2 * h + 0) * 128 + ql) * KNN;
        int lb = ((2 * h + 1) * 128 + ql) * KNN;
        float rd[KNN]; int rid[KNN];
        int pa = la, pb = lb;
#pragma unroll
        for (int j = 0; j < KNN; j++) {
            float va = sd[pa], vb = sd[pb];
            int   xa = si[pa], xb = si[pb];
            bool ta = (va < vb) || (va == vb && xa < xb);
            rd[j]  = ta ? va : vb;
            rid[j] = ta ? xa : xb;
            pa += ta ? 1 : 0;
            pb += ta ? 0 : 1;
        }
        int bo = ((2 * h) * 128 + ql) * KNN;
#pragma unroll
        for (int j = 0; j < KNN; j++) { sd[bo + j] = rd[j]; si[bo + j] = rid[j]; }
    }
    __syncthreads();

    // stage 2: h=0 merges slot 0 and slot 2, computes weights, stores
    if (h == 0) {
        int la = (0 * 128 + ql) * KNN;
        int lb = (2 * 128 + ql) * KNN;
        float rd[KNN]; int rid[KNN];
        int pa = la, pb = lb;
#pragma unroll
        for (int j = 0; j < KNN; j++) {
            float va = sd[pa], vb = sd[pb];
            int   xa = si[pa], xb = si[pb];
            bool ta = (va < vb) || (va == vb && xa < xb);
            rd[j]  = ta ? va : vb;
            rid[j] = ta ? xa : xb;
            pa += ta ? 1 : 0;
            pb += ta ? 0 : 1;
        }
        float r[KNN]; float sum = 0.f;
#pragma unroll
        for (int j = 0; j < KNN; j++) {
            r[j] = __fdiv_rn(1.0f, __fadd_rn(rd[j], 1e-8f));
            sum = __fadd_rn(sum, r[j]);
        }
#pragma unroll
        for (int j = 0; j < KNN; j++) {
            g_id[q * KNN + j] = rid[j];
            g_w[q * KNN + j]  = __fdiv_rn(r[j], sum);
        }
    }
}

// ============================================================
// 3) SGEMM (R3 scalar version): C[m,o]=sum_c A[m,c]*W[o,wcol0+c](+bias)
//    128x128 block tile, 8x8 per thread, K-chunks of 16
// ============================================================
__global__ void __launch_bounds__(256) gemm_kernel(
        const float* __restrict__ A, int K,
        const float* __restrict__ W, int wcol0,
        const float* __restrict__ bias, int dst)
{
    __shared__ float As[16][132];
    __shared__ float Bs[16][132];
    float* C = dst ? g_P : g_Q;

    int tid = threadIdx.x;
    int m0 = blockIdx.x * 128;
    int tx = tid & 15;
    int ty = tid >> 4;
    int lr = tid >> 2;
    int lc = (tid & 3) << 2;

    float acc[8][8];
#pragma unroll
    for (int i = 0; i < 8; i++)
#pragma unroll
        for (int j = 0; j < 8; j++) acc[i][j] = 0.f;

    for (int kt = 0; kt < K; kt += 16) {
        float4 a0 = *(const float4*)(A + (size_t)(m0 + lr) * K + kt + lc);
        float4 a1 = *(const float4*)(A + (size_t)(m0 + lr + 64) * K + kt + lc);
        float4 b0 = *(const float4*)(W + (size_t)lr * 384 + wcol0 + kt + lc);
        float4 b1 = *(const float4*)(W + (size_t)(lr + 64) * 384 + wcol0 + kt + lc);
        __syncthreads();
        As[lc + 0][lr] = a0.x; As[lc + 1][lr] = a0.y; As[lc + 2][lr] = a0.z; As[lc + 3][lr] = a0.w;
        As[lc + 0][lr + 64] = a1.x; As[lc + 1][lr + 64] = a1.y; As[lc + 2][lr + 64] = a1.z; As[lc + 3][lr + 64] = a1.w;
        Bs[lc + 0][lr] = b0.x; Bs[lc + 1][lr] = b0.y; Bs[lc + 2][lr] = b0.z; Bs[lc + 3][lr] = b0.w;
        Bs[lc + 0][lr + 64] = b1.x; Bs[lc + 1][lr + 64] = b1.y; Bs[lc + 2][lr + 64] = b1.z; Bs[lc + 3][lr + 64] = b1.w;
        __syncthreads();
#pragma unroll
        for (int kk = 0; kk < 16; kk++) {
            float4 af0 = *(float4*)&As[kk][ty * 4];
            float4 af1 = *(float4*)&As[kk][ty * 4 + 64];
            float4 bf0 = *(float4*)&Bs[kk][tx * 4];
            float4 bf1 = *(float4*)&Bs[kk][tx * 4 + 64];
            float av[8] = {af0.x, af0.y, af0.z, af0.w, af1.x, af1.y, af1.z, af1.w};
            float bv[8] = {bf0.x, bf0.y, bf0.z, bf0.w, bf1.x, bf1.y, bf1.z, bf1.w};
#pragma unroll
            for (int i = 0; i < 8; i++)
#pragma unroll
                for (int j = 0; j < 8; j++)
                    acc[i][j] = fmaf(av[i], bv[j], acc[i][j]);
        }
    }

    float bb[8] = {0.f, 0.f, 0.f, 0.f, 0.f, 0.f, 0.f, 0.f};
    if (bias) {
        float4 x0 = *(const float4*)(bias + tx * 4);
        float4 x1 = *(const float4*)(bias + tx * 4 + 64);
        bb[0] = x0.x; bb[1] = x0.y; bb[2] = x0.z; bb[3] = x0.w;
        bb[4] = x1.x; bb[5] = x1.y; bb[6] = x1.z; bb[7] = x1.w;
    }
#pragma unroll
    for (int i = 0; i < 8; i++) {
        int row = m0 + ty * 4 + (i < 4 ? i : 64 + i - 4);
        float4 v0 = make_float4(acc[i][0] + bb[0], acc[i][1] + bb[1],
                                acc[i][2] + bb[2], acc[i][3] + bb[3]);
        float4 v1 = make_float4(acc[i][4] + bb[4], acc[i][5] + bb[5],
                                acc[i][6] + bb[6], acc[i][7] + bb[7]);
        *(float4*)(C + (size_t)row * DOUT + tx * 4) = v0;
        *(float4*)(C + (size_t)row * DOUT + tx * 4 + 64) = v1;
    }
}

// ============================================================
// 4) combine: out[q,:] = Q[q,:] + sum_k w[q,k] * P[idx[q,k],:]
// ============================================================
__global__ void __launch_bounds__(128) combine_kernel(float* __restrict__ out) {
    int q = blockIdx.x;
    int tid = threadIdx.x;
    __shared__ float sw[KNN];
    __shared__ int   sid[KNN];
    if (tid < KNN) {
        sw[tid]  = g_w[q * KNN + tid];
        sid[tid] = g_id[q * KNN + tid];
    }
    __syncthreads();
    int base = q & ~(NPTS - 1);
    float acc = g_Q[(size_t)q * DOUT + tid];
#pragma unroll
    for (int j = 0; j < KNN; j++)
        acc = fmaf(sw[j], g_P[(size_t)(base + sid[j]) * DOUT + tid], acc);
    out[(size_t)q * DOUT + tid] = acc;
}

// ============================================================
// launcher: fork-join so GEMMs (independent of topk) overlap it.
//   main stream:  pack -> topk ------------\
//   side stream:  gemm(Q) -> gemm(P) ------+-> combine
// Streams/events are created lazily on the first (uncaptured)
// correctness call; capture sees only launches + event edges.
// ============================================================
static cudaStream_t s_side = nullptr;
static cudaEvent_t  s_evFork = nullptr, s_evJoin = nullptr;

extern "C" void kernel_launch(void* const* d_in, const int* in_sizes, int n_in,
                              void* d_out, int out_size) {
    const float* xyz1    = (const float*)d_in[0];
    const float* xyz2    = (const float*)d_in[1];
    const float* points1 = (const float*)d_in[2];
    const float* points2 = (const float*)d_in[3];
    const float* W       = (const float*)d_in[4];
    const float* bias    = (const float*)d_in[5];
    (void)in_sizes; (void)n_in; (void)out_size;

    if (s_side == nullptr) {
        cudaStreamCreateWithFlags(&s_side, cudaStreamNonBlocking);
        cudaEventCreateWithFlags(&s_evFork, cudaEventDisableTiming);
        cudaEventCreateWithFlags(&s_evJoin, cudaEventDisableTiming);
        cudaFuncSetAttribute(topk_kernel,
                             cudaFuncAttributeMaxDynamicSharedMemorySize, 196608);
    }

    // fork: side stream roots at current head of the main (capture) stream
    cudaEventRecord(s_evFork, 0);
    cudaStreamWaitEvent(s_side, s_evFork, 0);

    // side stream: the two GEMMs (depend only on points1/2, W, bias)
    gemm_kernel<<<NTOT / 128, 256, 0, s_side>>>(points1, 128, W, 0,   bias,    0); // g_Q
    gemm_kernel<<<NTOT / 128, 256, 0, s_side>>>(points2, 256, W, 128, nullptr, 1); // g_P
    cudaEventRecord(s_evJoin, s_side);

    // main stream: kNN pipeline
    pack_kernel<<<(NTOT + 255) / 256, 256>>>(xyz1);
    topk_kernel<<<NTOT / 128, 512, 196608>>>(xyz2);

    // join, then combine
    cudaStreamWaitEvent(0, s_evJoin, 0);
    combine_kernel<<<NTOT, 128>>>((float*)d_out);
}

// round 6
// speedup vs baseline: 4.5225x; 1.1605x over previous
#include <cuda_runtime.h>

#define NTOT 16384   // B*N
#define NPTS 8192    // N (per batch)
#define KNN  16
#define DOUT 128
#define SPLIT 4
#define LKEYS 2048   // NPTS / SPLIT
#define STKN 12      // per-lane candidate stack depth
#define FLUSH_AT 8   // flush when cnt >= 8
#define CHK 4        // check interval (keys)

// ---- scratch (__device__ globals: allocation-free) ----
__device__ float4 g_keys[NTOT];          // packed (x, y, z, ||k||^2)
__device__ float  g_Q[NTOT * DOUT];      // points1 @ W1^T + bias
__device__ float  g_P[NTOT * DOUT];      // points2 @ W2^T
__device__ int    g_id[NTOT * KNN];
__device__ float  g_w[NTOT * KNN];

// ============================================================
// 1) pack keys: (x, y, z, x^2+y^2+z^2) with reference rounding
// ============================================================
__global__ void pack_kernel(const float* __restrict__ xyz1) {
    int t = blockIdx.x * blockDim.x + threadIdx.x;
    if (t >= NTOT) return;
    float x = xyz1[3 * t + 0];
    float y = xyz1[3 * t + 1];
    float z = xyz1[3 * t + 2];
    float n = __fadd_rn(__fadd_rn(__fmul_rn(x, x), __fmul_rn(y, y)), __fmul_rn(z, z));
    g_keys[t] = make_float4(x, y, z, n);
}

// ============================================================
// 2) top-16 NN: 128 blocks x 512 threads, 4-way key split.
//    Per-lane 12-deep smem candidate stack (3-instr push),
//    flush-check every 4 keys, warp-uniform flush at cnt>=8.
//    Stack region is reused for the merge lists afterwards.
// ============================================================
__global__ void __launch_bounds__(512) topk_kernel(const float* __restrict__ xyz2) {
    extern __shared__ char smraw[];
    float4* skeys = (float4*)smraw;                        // 128KB
    float2* stk   = (float2*)(smraw + 131072);             // [12][512] = 48KB (main loop)
    float*  sd    = (float*)(smraw + 131072);              // 32KB (after stacks die)
    int*    si    = (int*)  (smraw + 131072 + 32768);      // 32KB (after stacks die)

    int tid = threadIdx.x;
    int ql  = tid & 127;          // local query
    int h   = tid >> 7;           // key quarter 0..3 (uniform per warp)
    int q   = blockIdx.x * 128 + ql;
    int b   = q >> 13;            // batch (uniform per block)

    const float4* gk = g_keys + (b << 13);
    for (int i = tid; i < NPTS; i += 512) skeys[i] = gk[i];
    __syncthreads();

    float qx = xyz2[3 * q + 0];
    float qy = xyz2[3 * q + 1];
    float qz = xyz2[3 * q + 2];
    float qn = __fadd_rn(__fadd_rn(__fmul_rn(qx, qx), __fmul_rn(qy, qy)),
                         __fmul_rn(qz, qz));

    const float FINF = __int_as_float(0x7f800000);

    float d[KNN];  int id[KNN];
#pragma unroll
    for (int j = 0; j < KNN; j++) { d[j] = 3.0e38f; id[j] = 0; }

    int cnt = 0;
    int k0 = h * LKEYS;

    for (int kk = 0; kk < LKEYS; kk += CHK) {
        if (__any_sync(0xffffffffu, cnt >= FLUSH_AT)) {
            for (int j = 0; j < STKN; j++) {
                if (!__any_sync(0xffffffffu, j < cnt)) break;
                float2 e = stk[j * 512 + tid];
                float cv = (j < cnt) ? e.x : FINF;
                int   ci = __float_as_int(e.y);
#pragma unroll
                for (int t = 0; t < KNN; t++) {
                    bool p = cv < d[t];
                    float od = d[t]; int oi = id[t];
                    d[t]  = p ? cv : od;
                    id[t] = p ? ci : oi;
                    cv    = p ? od : cv;
                    ci    = p ? oi : ci;
                }
            }
            cnt = 0;
        }
#pragma unroll
        for (int u = 0; u < CHK; u++) {
            int k = k0 + kk + u;
            float4 ky = skeys[k];                    // warp-broadcast LDS
            float dot = __fadd_rn(__fadd_rn(__fmul_rn(qx, ky.x), __fmul_rn(qy, ky.y)),
                                  __fmul_rn(qz, ky.z));
            float s = __fsub_rn(__fadd_rn(qn, ky.w), __fmul_rn(2.0f, dot));
            if (s < d[KNN - 1]) {                    // stale threshold: superset, safe
                stk[cnt * 512 + tid] = make_float2(s, __int_as_float(k));
                cnt++;
            }
        }
    }
    // final flush
    for (int j = 0; j < STKN; j++) {
        if (!__any_sync(0xffffffffu, j < cnt)) break;
        float2 e = stk[j * 512 + tid];
        float cv = (j < cnt) ? e.x : FINF;
        int   ci = __float_as_int(e.y);
#pragma unroll
        for (int t = 0; t < KNN; t++) {
            bool p = cv < d[t];
            float od = d[t]; int oi = id[t];
            d[t]  = p ? cv : od;
            id[t] = p ? ci : oi;
            cv    = p ? od : cv;
            ci    = p ? oi : ci;
        }
    }

    __syncthreads();   // all stacks dead; region becomes sd/si

    // publish partial lists
    int base = (h * 128 + ql) * KNN;
#pragma unroll
    for (int j = 0; j < KNN; j++) { sd[base + j] = d[j]; si[base + j] = id[j]; }
    __syncthreads();

    // stage 1: h=0 merges lists 0,1 -> slot 0 ; h=1 merges lists 2,3 -> slot 2
    if (h < 2) {
        int la = ((2 * h + 0) * 128 + ql) * KNN;
        int lb = ((2 * h + 1) * 128 + ql) * KNN;
        float rd[KNN]; int rid[KNN];
        int pa = la, pb = lb;
#pragma unroll
        for (int j = 0; j < KNN; j++) {
            float va = sd[pa], vb = sd[pb];
            int   xa = si[pa], xb = si[pb];
            bool ta = (va < vb) || (va == vb && xa < xb);
            rd[j]  = ta ? va : vb;
            rid[j] = ta ? xa : xb;
            pa += ta ? 1 : 0;
            pb += ta ? 0 : 1;
        }
        int bo = ((2 * h) * 128 + ql) * KNN;
#pragma unroll
        for (int j = 0; j < KNN; j++) { sd[bo + j] = rd[j]; si[bo + j] = rid[j]; }
    }
    __syncthreads();

    // stage 2: h=0 merges slot 0 and slot 2, computes weights, stores
    if (h == 0) {
        int la = (0 * 128 + ql) * KNN;
        int lb = (2 * 128 + ql) * KNN;
        float rd[KNN]; int rid[KNN];
        int pa = la, pb = lb;
#pragma unroll
        for (int j = 0; j < KNN; j++) {
            float va = sd[pa], vb = sd[pb];
            int   xa = si[pa], xb = si[pb];
            bool ta = (va < vb) || (va == vb && xa < xb);
            rd[j]  = ta ? va : vb;
            rid[j] = ta ? xa : xb;
            pa += ta ? 1 : 0;
            pb += ta ? 0 : 1;
        }
        float r[KNN]; float sum = 0.f;
#pragma unroll
        for (int j = 0; j < KNN; j++) {
            r[j] = __fdiv_rn(1.0f, __fadd_rn(rd[j], 1e-8f));
            sum = __fadd_rn(sum, r[j]);
        }
#pragma unroll
        for (int j = 0; j < KNN; j++) {
            g_id[q * KNN + j] = rid[j];
            g_w[q * KNN + j]  = __fdiv_rn(r[j], sum);
        }
    }
}

// ============================================================
// 3) SGEMM: C[m,o]=sum_c A[m,c]*W[o,wcol0+c](+bias)
//    128x128 block tile, 8x8 per thread, K-chunks of 16
// ============================================================
__global__ void __launch_bounds__(256) gemm_kernel(
        const float* __restrict__ A, int K,
        const float* __restrict__ W, int wcol0,
        const float* __restrict__ bias, int dst)
{
    __shared__ float As[16][132];
    __shared__ float Bs[16][132];
    float* C = dst ? g_P : g_Q;

    int tid = threadIdx.x;
    int m0 = blockIdx.x * 128;
    int tx = tid & 15;
    int ty = tid >> 4;
    int lr = tid >> 2;
    int lc = (tid & 3) << 2;

    float acc[8][8];
#pragma unroll
    for (int i = 0; i < 8; i++)
#pragma unroll
        for (int j = 0; j < 8; j++) acc[i][j] = 0.f;

    for (int kt = 0; kt < K; kt += 16) {
        float4 a0 = *(const float4*)(A + (size_t)(m0 + lr) * K + kt + lc);
        float4 a1 = *(const float4*)(A + (size_t)(m0 + lr + 64) * K + kt + lc);
        float4 b0 = *(const float4*)(W + (size_t)lr * 384 + wcol0 + kt + lc);
        float4 b1 = *(const float4*)(W + (size_t)(lr + 64) * 384 + wcol0 + kt + lc);
        __syncthreads();
        As[lc + 0][lr] = a0.x; As[lc + 1][lr] = a0.y; As[lc + 2][lr] = a0.z; As[lc + 3][lr] = a0.w;
        As[lc + 0][lr + 64] = a1.x; As[lc + 1][lr + 64] = a1.y; As[lc + 2][lr + 64] = a1.z; As[lc + 3][lr + 64] = a1.w;
        Bs[lc + 0][lr] = b0.x; Bs[lc + 1][lr] = b0.y; Bs[lc + 2][lr] = b0.z; Bs[lc + 3][lr] = b0.w;
        Bs[lc + 0][lr + 64] = b1.x; Bs[lc + 1][lr + 64] = b1.y; Bs[lc + 2][lr + 64] = b1.z; Bs[lc + 3][lr + 64] = b1.w;
        __syncthreads();
#pragma unroll
        for (int kk = 0; kk < 16; kk++) {
            float4 af0 = *(float4*)&As[kk][ty * 4];
            float4 af1 = *(float4*)&As[kk][ty * 4 + 64];
            float4 bf0 = *(float4*)&Bs[kk][tx * 4];
            float4 bf1 = *(float4*)&Bs[kk][tx * 4 + 64];
            float av[8] = {af0.x, af0.y, af0.z, af0.w, af1.x, af1.y, af1.z, af1.w};
            float bv[8] = {bf0.x, bf0.y, bf0.z, bf0.w, bf1.x, bf1.y, bf1.z, bf1.w};
#pragma unroll
            for (int i = 0; i < 8; i++)
#pragma unroll
                for (int j = 0; j < 8; j++)
                    acc[i][j] = fmaf(av[i], bv[j], acc[i][j]);
        }
    }

    float bb[8] = {0.f, 0.f, 0.f, 0.f, 0.f, 0.f, 0.f, 0.f};
    if (bias) {
        float4 x0 = *(const float4*)(bias + tx * 4);
        float4 x1 = *(const float4*)(bias + tx * 4 + 64);
        bb[0] = x0.x; bb[1] = x0.y; bb[2] = x0.z; bb[3] = x0.w;
        bb[4] = x1.x; bb[5] = x1.y; bb[6] = x1.z; bb[7] = x1.w;
    }
#pragma unroll
    for (int i = 0; i < 8; i++) {
        int row = m0 + ty * 4 + (i < 4 ? i : 64 + i - 4);
        float4 v0 = make_float4(acc[i][0] + bb[0], acc[i][1] + bb[1],
                                acc[i][2] + bb[2], acc[i][3] + bb[3]);
        float4 v1 = make_float4(acc[i][4] + bb[4], acc[i][5] + bb[5],
                                acc[i][6] + bb[6], acc[i][7] + bb[7]);
        *(float4*)(C + (size_t)row * DOUT + tx * 4) = v0;
        *(float4*)(C + (size_t)row * DOUT + tx * 4 + 64) = v1;
    }
}

// ============================================================
// 4) combine: out[q,:] = Q[q,:] + sum_k w[q,k] * P[idx[q,k],:]
// ============================================================
__global__ void __launch_bounds__(128) combine_kernel(float* __restrict__ out) {
    int q = blockIdx.x;
    int tid = threadIdx.x;
    __shared__ float sw[KNN];
    __shared__ int   sid[KNN];
    if (tid < KNN) {
        sw[tid]  = g_w[q * KNN + tid];
        sid[tid] = g_id[q * KNN + tid];
    }
    __syncthreads();
    int base = q & ~(NPTS - 1);
    float acc = g_Q[(size_t)q * DOUT + tid];
#pragma unroll
    for (int j = 0; j < KNN; j++)
        acc = fmaf(sw[j], g_P[(size_t)(base + sid[j]) * DOUT + tid], acc);
    out[(size_t)q * DOUT + tid] = acc;
}

// ============================================================
// launcher: fork-join so GEMMs (independent of topk) overlap it.
// ============================================================
static cudaStream_t s_side = nullptr;
static cudaEvent_t  s_evFork = nullptr, s_evJoin = nullptr;

extern "C" void kernel_launch(void* const* d_in, const int* in_sizes, int n_in,
                              void* d_out, int out_size) {
    const float* xyz1    = (const float*)d_in[0];
    const float* xyz2    = (const float*)d_in[1];
    const float* points1 = (const float*)d_in[2];
    const float* points2 = (const float*)d_in[3];
    const float* W       = (const float*)d_in[4];
    const float* bias    = (const float*)d_in[5];
    (void)in_sizes; (void)n_in; (void)out_size;

    if (s_side == nullptr) {
        cudaStreamCreateWithFlags(&s_side, cudaStreamNonBlocking);
        cudaEventCreateWithFlags(&s_evFork, cudaEventDisableTiming);
        cudaEventCreateWithFlags(&s_evJoin, cudaEventDisableTiming);
        cudaFuncSetAttribute(topk_kernel,
                             cudaFuncAttributeMaxDynamicSharedMemorySize, 196608);
    }

    // fork: side stream roots at current head of the main (capture) stream
    cudaEventRecord(s_evFork, 0);
    cudaStreamWaitEvent(s_side, s_evFork, 0);

    // side stream: the two GEMMs (depend only on points1/2, W, bias)
    gemm_kernel<<<NTOT / 128, 256, 0, s_side>>>(points1, 128, W, 0,   bias,    0); // g_Q
    gemm_kernel<<<NTOT / 128, 256, 0, s_side>>>(points2, 256, W, 128, nullptr, 1); // g_P
    cudaEventRecord(s_evJoin, s_side);

    // main stream: kNN pipeline
    pack_kernel<<<(NTOT + 255) / 256, 256>>>(xyz1);
    topk_kernel<<<NTOT / 128, 512, 196608>>>(xyz2);

    // join, then combine
    cudaStreamWaitEvent(0, s_evJoin, 0);
    combine_kernel<<<NTOT, 128>>>((float*)d_out);
}